// round 3
// baseline (speedup 1.0000x reference)
#include <cuda_runtime.h>
#include <cuda_bf16.h>
#include <cstdint>

// Problem shapes (fixed by the reference):
//   tex_batch: [16, 3, 512, 512] float32   (d_in[0])
//   iuv_img:   [16, 3, 768, 768] int32     (d_in[1])
//   lut:       [25, 256, 256, 2] float32   (d_in[2])
//   out:       [16, 3, 768, 768] float32
#define NB 16
#define NC 3
#define TH 512
#define TW 512
#define OH 768
#define OW 768
#define TPLANE (TH * TW)      // 262144
#define OPLANE (OH * OW)      // 589824
#define LUT_I 25

// Packed interleaved texture: [B, H, W] of float4 {c0, c1, c2, 0}.
// 16 * 512 * 512 * 16B = 64 MB device scratch (static, allocation-free).
__device__ float4 g_tex4[NB * TPLANE];

// ---------------------------------------------------------------------------
// Kernel A: pack planar [B,3,512,512] -> interleaved float4 [B,512,512]
// Pure streaming: 50 MB read + 64 MB write.
// ---------------------------------------------------------------------------
__global__ void __launch_bounds__(256) pack_tex_kernel(const float* __restrict__ tex)
{
    int idx = blockIdx.x * blockDim.x + threadIdx.x;
    if (idx >= NB * TPLANE) return;
    int b = idx / TPLANE;
    int p = idx - b * TPLANE;
    const float* base = tex + (size_t)b * NC * TPLANE + p;
    float4 v;
    v.x = __ldg(base);
    v.y = __ldg(base + TPLANE);
    v.z = __ldg(base + 2 * TPLANE);
    v.w = 0.0f;
    g_tex4[idx] = v;
}

// ---------------------------------------------------------------------------
// Per-pixel sampling: LUT gather + bilinear grid-sample (align_corners=True,
// zeros padding) from the packed float4 texture. fp32 op order mirrors the
// reference exactly.
// ---------------------------------------------------------------------------
__device__ __forceinline__ void sample_one(
    int i, int uraw, int vraw,
    const float2* __restrict__ lut,
    const float4* __restrict__ tb,   // per-batch packed texture base
    float& r0, float& r1, float& r2)
{
    // i index into lut: JAX clamps OOB gather indices.
    i = min(max(i, 0), LUT_I - 1);
    float u = fminf(fmaxf((float)uraw * (1.0f / 255.0f), 0.0f), 1.0f);
    float v = fminf(fmaxf((float)vraw * (1.0f / 255.0f), 0.0f), 1.0f);
    int ui = __float2int_rn(u * 255.0f);
    int vi = __float2int_rn(v * 255.0f);

    float2 uv = __ldg(lut + (((i << 8) + vi) << 8) + ui);

    // grid coords, replicating reference op order
    float u_I = uv.x * 2.0f - 1.0f;
    float v_I = (1.0f - uv.y) * 2.0f - 1.0f;
    float x = (u_I + 1.0f) * 0.5f * (float)(TW - 1);
    float y = (v_I + 1.0f) * 0.5f * (float)(TH - 1);

    float x0f = floorf(x);
    float y0f = floorf(y);
    float wx = x - x0f;
    float wy = y - y0f;
    int x0 = (int)x0f, y0 = (int)y0f;
    int x1 = x0 + 1,  y1 = y0 + 1;

    // zeros padding: zero the weight of invalid corners, clamp fetch index
    float a00 = (1.0f - wy) * (1.0f - wx);
    float a01 = (1.0f - wy) * wx;
    float a10 = wy * (1.0f - wx);
    float a11 = wy * wx;

    bool vx0 = (x0 >= 0) & (x0 < TW);
    bool vx1 = (x1 >= 0) & (x1 < TW);
    bool vy0 = (y0 >= 0) & (y0 < TH);
    bool vy1 = (y1 >= 0) & (y1 < TH);
    a00 = (vy0 & vx0) ? a00 : 0.0f;
    a01 = (vy0 & vx1) ? a01 : 0.0f;
    a10 = (vy1 & vx0) ? a10 : 0.0f;
    a11 = (vy1 & vx1) ? a11 : 0.0f;

    int cx0 = min(max(x0, 0), TW - 1);
    int cx1 = min(max(x1, 0), TW - 1);
    int cy0 = min(max(y0, 0), TH - 1);
    int cy1 = min(max(y1, 0), TH - 1);

    float4 t00 = __ldg(tb + cy0 * TW + cx0);
    float4 t01 = __ldg(tb + cy0 * TW + cx1);
    float4 t10 = __ldg(tb + cy1 * TW + cx0);
    float4 t11 = __ldg(tb + cy1 * TW + cx1);

    r0 = t00.x * a00 + t01.x * a01 + t10.x * a10 + t11.x * a11;
    r1 = t00.y * a00 + t01.y * a01 + t10.y * a10 + t11.y * a11;
    r2 = t00.z * a00 + t01.z * a01 + t10.z * a10 + t11.z * a11;
}

// ---------------------------------------------------------------------------
// Kernel B: one thread handles 4 consecutive output pixels.
// IUV loads are int4 (16B, coalesced), output stores are float4 per plane.
// ---------------------------------------------------------------------------
__global__ void __launch_bounds__(256) densepose_sample_kernel(
    const int* __restrict__ iuv,
    const float2* __restrict__ lut,
    float* __restrict__ out)
{
    int t = blockIdx.x * blockDim.x + threadIdx.x;
    const int quads_per_img = OPLANE / 4;               // 147456
    if (t >= NB * quads_per_img) return;
    int b = t / quads_per_img;
    int q = t - b * quads_per_img;
    int p = q * 4;                                       // pixel offset in plane

    const int* ib = iuv + (size_t)b * 3 * OPLANE + p;
    int4 iq = *reinterpret_cast<const int4*>(ib);                 // i channel
    int4 uq = *reinterpret_cast<const int4*>(ib + OPLANE);        // u channel
    int4 vq = *reinterpret_cast<const int4*>(ib + 2 * OPLANE);    // v channel

    const float4* tb = g_tex4 + (size_t)b * TPLANE;

    float4 o0, o1, o2;
    sample_one(iq.x, uq.x, vq.x, lut, tb, o0.x, o1.x, o2.x);
    sample_one(iq.y, uq.y, vq.y, lut, tb, o0.y, o1.y, o2.y);
    sample_one(iq.z, uq.z, vq.z, lut, tb, o0.z, o1.z, o2.z);
    sample_one(iq.w, uq.w, vq.w, lut, tb, o0.w, o1.w, o2.w);

    float* ob = out + (size_t)b * 3 * OPLANE + p;
    *reinterpret_cast<float4*>(ob)              = o0;
    *reinterpret_cast<float4*>(ob + OPLANE)     = o1;
    *reinterpret_cast<float4*>(ob + 2 * OPLANE) = o2;
}

extern "C" void kernel_launch(void* const* d_in, const int* in_sizes, int n_in,
                              void* d_out, int out_size)
{
    const float* tex = (const float*)d_in[0];
    const int*   iuv = (const int*)d_in[1];
    const float2* lut = (const float2*)d_in[2];
    float* out = (float*)d_out;

    {
        int n = NB * TPLANE;
        pack_tex_kernel<<<(n + 255) / 256, 256>>>(tex);
    }
    {
        int n = NB * (OPLANE / 4);
        densepose_sample_kernel<<<(n + 255) / 256, 256>>>(iuv, lut, out);
    }
}

// round 6
// speedup vs baseline: 1.3879x; 1.3879x over previous
#include <cuda_runtime.h>
#include <cuda_bf16.h>
#include <cstdint>

// Shapes (fixed by the reference):
//   tex_batch: [16, 3, 512, 512] float32   (d_in[0])
//   iuv_img:   [16, 3, 768, 768] int32     (d_in[1])
//   lut:       [25, 256, 256, 2] float32   (d_in[2])
//   out:       [16, 3, 768, 768] float32
#define NB 16
#define NC 3
#define TH 512
#define TW 512
#define OH 768
#define OW 768
#define TPLANE (TH * TW)      // 262144
#define OPLANE (OH * OW)      // 589824
#define LUT_I 25
#define NT (25 * 25 * 25)     // 15625 distinct (i,vi,ui) triples

// Precomputed color table: T[b][i*625 + vi*25 + ui] = {c0,c1,c2,0}.
// 16 * 15625 * 16B = 4 MB static device scratch (allocation-free).
__device__ float4 g_table[NB * NT];

// ---------------------------------------------------------------------------
// Bilinear grid-sample (align_corners=True, zeros padding) from the planar
// texture, given a LUT entry. fp32 op order mirrors the reference exactly.
// tb = tex + b*3*TPLANE (planar, channel stride TPLANE).
// ---------------------------------------------------------------------------
__device__ __forceinline__ void bilinear_from_uv(
    float2 uv, const float* __restrict__ tb,
    float& r0, float& r1, float& r2)
{
    float u_I = uv.x * 2.0f - 1.0f;
    float v_I = (1.0f - uv.y) * 2.0f - 1.0f;
    float x = (u_I + 1.0f) * 0.5f * (float)(TW - 1);
    float y = (v_I + 1.0f) * 0.5f * (float)(TH - 1);

    float x0f = floorf(x);
    float y0f = floorf(y);
    float wx = x - x0f;
    float wy = y - y0f;
    int x0 = (int)x0f, y0 = (int)y0f;
    int x1 = x0 + 1,  y1 = y0 + 1;

    float a00 = (1.0f - wy) * (1.0f - wx);
    float a01 = (1.0f - wy) * wx;
    float a10 = wy * (1.0f - wx);
    float a11 = wy * wx;

    bool vx0 = (x0 >= 0) & (x0 < TW);
    bool vx1 = (x1 >= 0) & (x1 < TW);
    bool vy0 = (y0 >= 0) & (y0 < TH);
    bool vy1 = (y1 >= 0) & (y1 < TH);
    a00 = (vy0 & vx0) ? a00 : 0.0f;
    a01 = (vy0 & vx1) ? a01 : 0.0f;
    a10 = (vy1 & vx0) ? a10 : 0.0f;
    a11 = (vy1 & vx1) ? a11 : 0.0f;

    int cx0 = min(max(x0, 0), TW - 1);
    int cx1 = min(max(x1, 0), TW - 1);
    int cy0 = min(max(y0, 0), TH - 1);
    int cy1 = min(max(y1, 0), TH - 1);

    int o00 = cy0 * TW + cx0;
    int o01 = cy0 * TW + cx1;
    int o10 = cy1 * TW + cx0;
    int o11 = cy1 * TW + cx1;

    r0 = __ldg(tb + o00) * a00 + __ldg(tb + o01) * a01
       + __ldg(tb + o10) * a10 + __ldg(tb + o11) * a11;
    const float* tb1 = tb + TPLANE;
    r1 = __ldg(tb1 + o00) * a00 + __ldg(tb1 + o01) * a01
       + __ldg(tb1 + o10) * a10 + __ldg(tb1 + o11) * a11;
    const float* tb2 = tb + 2 * TPLANE;
    r2 = __ldg(tb2 + o00) * a00 + __ldg(tb2 + o01) * a01
       + __ldg(tb2 + o10) * a10 + __ldg(tb2 + o11) * a11;
}

// ---------------------------------------------------------------------------
// Kernel A: build the 250K-entry color table.
// One thread per (b, triple). ~3M scalar gathers total — negligible.
// ---------------------------------------------------------------------------
__global__ void __launch_bounds__(256) build_table_kernel(
    const float* __restrict__ tex,
    const float2* __restrict__ lut)
{
    int e = blockIdx.x * blockDim.x + threadIdx.x;
    if (e >= NB * NT) return;
    int b = e / NT;
    int t = e - b * NT;
    int i  = t / 625;
    int r  = t - i * 625;
    int vi = r / 25;
    int ui = r - vi * 25;

    float2 uv = __ldg(lut + (((i << 8) + vi) << 8) + ui);
    const float* tb = tex + (size_t)b * NC * TPLANE;
    float r0, r1, r2;
    bilinear_from_uv(uv, tb, r0, r1, r2);
    g_table[e] = make_float4(r0, r1, r2, 0.0f);
}

// ---------------------------------------------------------------------------
// Slow path for u/v outside [0,24] — never taken with this data.
// __noinline__ keeps the fast path's register allocation lean.
// ---------------------------------------------------------------------------
__device__ __noinline__ void sample_slow(
    int i, int uraw, int vraw,
    const float2* __restrict__ lut,
    const float* __restrict__ tb,
    float& r0, float& r1, float& r2)
{
    i = min(max(i, 0), LUT_I - 1);
    float u = fminf(fmaxf((float)uraw * (1.0f / 255.0f), 0.0f), 1.0f);
    float v = fminf(fmaxf((float)vraw * (1.0f / 255.0f), 0.0f), 1.0f);
    int ui = __float2int_rn(u * 255.0f);
    int vi = __float2int_rn(v * 255.0f);
    float2 uv = __ldg(lut + (((i << 8) + vi) << 8) + ui);
    bilinear_from_uv(uv, tb, r0, r1, r2);
}

// ---------------------------------------------------------------------------
// Kernel B: main sampling. One thread = 4 consecutive output pixels.
// Per pixel: one 16B gather from the 4MB L2-resident table.
// ---------------------------------------------------------------------------
__global__ void __launch_bounds__(256) densepose_sample_kernel(
    const int* __restrict__ iuv,
    const float2* __restrict__ lut,
    const float* __restrict__ tex,
    float* __restrict__ out)
{
    int t = blockIdx.x * blockDim.x + threadIdx.x;
    const int quads_per_img = OPLANE / 4;               // 147456
    if (t >= NB * quads_per_img) return;
    int b = t / quads_per_img;
    int q = t - b * quads_per_img;
    int p = q * 4;

    const int* ib = iuv + (size_t)b * 3 * OPLANE + p;
    int4 iq = *reinterpret_cast<const int4*>(ib);
    int4 uq = *reinterpret_cast<const int4*>(ib + OPLANE);
    int4 vq = *reinterpret_cast<const int4*>(ib + 2 * OPLANE);

    const float4* Tb = g_table + b * NT;
    const float*  tb = tex + (size_t)b * NC * TPLANE;

    float4 o0, o1, o2;

    {
        int ii = min(max(iq.x, 0), LUT_I - 1);
        if (((unsigned)uq.x <= 24u) & ((unsigned)vq.x <= 24u)) {
            float4 c = __ldg(Tb + ii * 625 + vq.x * 25 + uq.x);
            o0.x = c.x; o1.x = c.y; o2.x = c.z;
        } else {
            sample_slow(iq.x, uq.x, vq.x, lut, tb, o0.x, o1.x, o2.x);
        }
    }
    {
        int ii = min(max(iq.y, 0), LUT_I - 1);
        if (((unsigned)uq.y <= 24u) & ((unsigned)vq.y <= 24u)) {
            float4 c = __ldg(Tb + ii * 625 + vq.y * 25 + uq.y);
            o0.y = c.x; o1.y = c.y; o2.y = c.z;
        } else {
            sample_slow(iq.y, uq.y, vq.y, lut, tb, o0.y, o1.y, o2.y);
        }
    }
    {
        int ii = min(max(iq.z, 0), LUT_I - 1);
        if (((unsigned)uq.z <= 24u) & ((unsigned)vq.z <= 24u)) {
            float4 c = __ldg(Tb + ii * 625 + vq.z * 25 + uq.z);
            o0.z = c.x; o1.z = c.y; o2.z = c.z;
        } else {
            sample_slow(iq.z, uq.z, vq.z, lut, tb, o0.z, o1.z, o2.z);
        }
    }
    {
        int ii = min(max(iq.w, 0), LUT_I - 1);
        if (((unsigned)uq.w <= 24u) & ((unsigned)vq.w <= 24u)) {
            float4 c = __ldg(Tb + ii * 625 + vq.w * 25 + uq.w);
            o0.w = c.x; o1.w = c.y; o2.w = c.z;
        } else {
            sample_slow(iq.w, uq.w, vq.w, lut, tb, o0.w, o1.w, o2.w);
        }
    }

    float* ob = out + (size_t)b * 3 * OPLANE + p;
    *reinterpret_cast<float4*>(ob)              = o0;
    *reinterpret_cast<float4*>(ob + OPLANE)     = o1;
    *reinterpret_cast<float4*>(ob + 2 * OPLANE) = o2;
}

extern "C" void kernel_launch(void* const* d_in, const int* in_sizes, int n_in,
                              void* d_out, int out_size)
{
    const float*  tex = (const float*)d_in[0];
    const int*    iuv = (const int*)d_in[1];
    const float2* lut = (const float2*)d_in[2];
    float* out = (float*)d_out;

    {
        int n = NB * NT;
        build_table_kernel<<<(n + 255) / 256, 256>>>(tex, lut);
    }
    {
        int n = NB * (OPLANE / 4);
        densepose_sample_kernel<<<(n + 255) / 256, 256>>>(iuv, lut, tex, out);
    }
}